// round 1
// baseline (speedup 1.0000x reference)
#include <cuda_runtime.h>

#define N_NODES    500000
#define D          256
#define N_IDENT    50000
#define N_ID       150000
#define N_PRIM     60000
#define N_MOD      30000
#define NT_VOCAB   120
#define PV         16
#define MV         16

// Scratch (allocation-free rule: __device__ globals)
__device__ float g_Y[N_IDENT * D];        // identifiers @ W_id[:, :256]^T
__device__ float g_Tid[NT_VOCAB * D];     // table @ W_id[:, 256:]^T + b_id
__device__ float g_Tprim[NT_VOCAB * D];   // table @ W_prim[:, 64:]^T + b_prim
__device__ float g_Tmod[NT_VOCAB * D];    // table @ W_mod[:, 64:]^T + b_mod
__device__ float g_P[PV * D];             // prim_table @ W_prim[:, :64]^T
__device__ float g_M[MV * D];             // mod_table  @ W_mod[:, :64]^T
__device__ int   g_flag[N_NODES];

// ---------------------------------------------------------------------------
// Y[M=50000, N=256] = X[M, 256] @ W[:, :256]^T   (W row-major [256 x 512])
// 64x64 tile per 256-thread block, 4x4 per thread, BK=16.
// ---------------------------------------------------------------------------
__global__ __launch_bounds__(256) void gemm_y_kernel(
    const float* __restrict__ X, const float* __restrict__ W)
{
    __shared__ float Xs[16][68];   // [k][m], row stride 68 floats = 272B (16B aligned)
    __shared__ float Ws[16][68];   // [k][n]

    const int bm  = blockIdx.x * 64;
    const int bn  = blockIdx.y * 64;
    const int tid = threadIdx.x;
    const int tx  = tid & 15;      // col group
    const int ty  = tid >> 4;      // row group
    const int lk  = tid & 15;      // loader: k index
    const int lr  = tid >> 4;      // loader: base row/col

    float acc[4][4];
#pragma unroll
    for (int i = 0; i < 4; i++)
#pragma unroll
        for (int j = 0; j < 4; j++) acc[i][j] = 0.f;

    for (int k0 = 0; k0 < 256; k0 += 16) {
#pragma unroll
        for (int i = 0; i < 4; i++) {
            int m  = lr + i * 16;
            int gm = bm + m;
            Xs[lk][m] = (gm < N_IDENT) ? X[gm * 256 + k0 + lk] : 0.f;
            Ws[lk][m] = W[(bn + m) * 512 + k0 + lk];
        }
        __syncthreads();
#pragma unroll
        for (int k = 0; k < 16; k++) {
            float4 a = *(const float4*)(&Xs[k][ty * 4]);
            float4 b = *(const float4*)(&Ws[k][tx * 4]);
            float av[4] = {a.x, a.y, a.z, a.w};
            float bv[4] = {b.x, b.y, b.z, b.w};
#pragma unroll
            for (int i = 0; i < 4; i++)
#pragma unroll
                for (int j = 0; j < 4; j++) acc[i][j] += av[i] * bv[j];
        }
        __syncthreads();
    }

#pragma unroll
    for (int i = 0; i < 4; i++) {
        int gm = bm + ty * 4 + i;
        if (gm < N_IDENT) {
            float4 v = make_float4(acc[i][0], acc[i][1], acc[i][2], acc[i][3]);
            *(float4*)(&g_Y[gm * 256 + bn + tx * 4]) = v;
        }
    }
}

// ---------------------------------------------------------------------------
// out[v, o] = sum_k tbl[v*K+k] * W[o*wstride + woff + k]  (+ b[o])
// grid = V blocks, 256 threads (o = tid). sel picks destination global.
// ---------------------------------------------------------------------------
__global__ void small_lin_kernel(
    const float* __restrict__ tbl, int K,
    const float* __restrict__ W, int wstride, int woff,
    const float* __restrict__ b, int sel)
{
    int v = blockIdx.x;
    int o = threadIdx.x;
    float s = (b != nullptr) ? b[o] : 0.f;
    const float* trow = tbl + v * K;
    const float* wrow = W + o * wstride + woff;
    for (int k = 0; k < K; k++) s += trow[k] * wrow[k];
    float* dst;
    switch (sel) {
        case 0: dst = g_Tid;   break;
        case 1: dst = g_Tprim; break;
        case 2: dst = g_Tmod;  break;
        case 3: dst = g_P;     break;
        default: dst = g_M;    break;
    }
    dst[v * D + o] = s;
}

__global__ void init_flags_kernel()
{
    int n = blockIdx.x * blockDim.x + threadIdx.x;
    if (n < N_NODES) g_flag[n] = -1;
}

__global__ void set_flags_kernel(
    const int* __restrict__ id_node, const int* __restrict__ prim_node,
    const int* __restrict__ mod_node)
{
    int i = blockIdx.x * blockDim.x + threadIdx.x;
    if (i < N_ID) {
        g_flag[id_node[i]] = i;                              // kind 0
    } else if (i < N_ID + N_PRIM) {
        int j = i - N_ID;
        g_flag[prim_node[j]] = (1 << 28) | j;                // kind 1
    } else if (i < N_ID + N_PRIM + N_MOD) {
        int j = i - N_ID - N_PRIM;
        g_flag[mod_node[j]] = (2 << 28) | j;                 // kind 2
    }
}

// ---------------------------------------------------------------------------
// One float4 per thread, 64 threads per node row.
// ---------------------------------------------------------------------------
__global__ __launch_bounds__(256) void finalize_kernel(
    const float4* __restrict__ tbl4,
    const int* __restrict__ types,
    const int* __restrict__ id_ident,
    const int* __restrict__ prim_types,
    const int* __restrict__ mod_ids,
    float4* __restrict__ out4)
{
    long long idx = (long long)blockIdx.x * 256 + threadIdx.x;
    int node = (int)(idx >> 6);
    int c    = (int)(idx & 63);
    if (node >= N_NODES) return;

    int f = g_flag[node];
    int t = types[node];
    float4 r;
    if (f < 0) {
        r = tbl4[t * 64 + c];
    } else {
        int kind = f >> 28;
        int row  = f & 0x0FFFFFFF;
        float4 x, y;
        if (kind == 0) {
            x = ((const float4*)g_Y)[(long long)id_ident[row] * 64 + c];
            y = ((const float4*)g_Tid)[t * 64 + c];
        } else if (kind == 1) {
            x = ((const float4*)g_P)[prim_types[row] * 64 + c];
            y = ((const float4*)g_Tprim)[t * 64 + c];
        } else {
            x = ((const float4*)g_M)[mod_ids[row] * 64 + c];
            y = ((const float4*)g_Tmod)[t * 64 + c];
        }
        r = make_float4(x.x + y.x, x.y + y.y, x.z + y.z, x.w + y.w);
    }
    out4[(long long)node * 64 + c] = r;
}

extern "C" void kernel_launch(void* const* d_in, const int* in_sizes, int n_in,
                              void* d_out, int out_size)
{
    const float* identifiers = (const float*)d_in[0];   // [50000, 256]
    const float* node_table  = (const float*)d_in[1];   // [120, 256]
    const float* prim_table  = (const float*)d_in[2];   // [16, 64]
    const float* mod_table   = (const float*)d_in[3];   // [16, 64]
    const float* W_id        = (const float*)d_in[4];   // [256, 512]
    const float* b_id        = (const float*)d_in[5];   // [256]
    const float* W_prim      = (const float*)d_in[6];   // [256, 320]
    const float* b_prim      = (const float*)d_in[7];   // [256]
    const float* W_mod       = (const float*)d_in[8];   // [256, 320]
    const float* b_mod       = (const float*)d_in[9];   // [256]
    const int*   types       = (const int*)d_in[10];    // [500000]
    const int*   id_ident    = (const int*)d_in[11];    // [150000]
    const int*   id_node     = (const int*)d_in[12];    // [150000]
    const int*   prim_types  = (const int*)d_in[13];    // [60000]
    const int*   prim_node   = (const int*)d_in[14];    // [60000]
    const int*   mod_ids     = (const int*)d_in[15];    // [30000]
    const int*   mod_node    = (const int*)d_in[16];    // [30000]
    float*       out         = (float*)d_out;

    // Flags: inverse map node -> (kind, leaf row)
    init_flags_kernel<<<(N_NODES + 255) / 256, 256>>>();
    {
        int total = N_ID + N_PRIM + N_MOD;
        set_flags_kernel<<<(total + 255) / 256, 256>>>(id_node, prim_node, mod_node);
    }

    // Tiny precomputes
    small_lin_kernel<<<NT_VOCAB, 256>>>(node_table, 256, W_id,   512, 256, b_id,   0);
    small_lin_kernel<<<NT_VOCAB, 256>>>(node_table, 256, W_prim, 320, 64,  b_prim, 1);
    small_lin_kernel<<<NT_VOCAB, 256>>>(node_table, 256, W_mod,  320, 64,  b_mod,  2);
    small_lin_kernel<<<PV,       256>>>(prim_table, 64,  W_prim, 320, 0,   nullptr, 3);
    small_lin_kernel<<<MV,       256>>>(mod_table,  64,  W_mod,  320, 0,   nullptr, 4);

    // Main GEMM: Y = identifiers @ W_id[:, :256]^T
    {
        dim3 grid((N_IDENT + 63) / 64, 256 / 64);
        gemm_y_kernel<<<grid, 256>>>(identifiers, W_id);
    }

    // Fused output pass
    {
        long long total = (long long)N_NODES * 64;
        int blocks = (int)((total + 255) / 256);
        finalize_kernel<<<blocks, 256>>>(
            (const float4*)node_table, types, id_ident, prim_types, mod_ids,
            (float4*)out);
    }
}

// round 2
// speedup vs baseline: 1.2820x; 1.2820x over previous
#include <cuda_runtime.h>

#define N_NODES    500000
#define D          256
#define N_IDENT    50000
#define N_ID       150000
#define N_PRIM     60000
#define N_MOD      30000
#define NT_VOCAB   120
#define PV         16
#define MV         16

// Scratch (allocation-free rule: __device__ globals)
__device__ float g_Y[N_IDENT * D];        // identifiers @ W_id[:, :256]^T
__device__ float g_Tid[NT_VOCAB * D];     // table @ W_id[:, 256:]^T + b_id
__device__ float g_Tprim[NT_VOCAB * D];   // table @ W_prim[:, 64:]^T + b_prim
__device__ float g_Tmod[NT_VOCAB * D];    // table @ W_mod[:, 64:]^T + b_mod
__device__ float g_P[PV * D];             // prim_table @ W_prim[:, :64]^T
__device__ float g_M[MV * D];             // mod_table  @ W_mod[:, :64]^T
__device__ int   g_flag[N_NODES];

// ---------------------------------------------------------------------------
// Y[M=50000, N=256] = X[M, 256] @ W[:, :256]^T   (W row-major [256 x 512])
// 64x64 tile per 256-thread block, 4x4 per thread, BK=16.
// ---------------------------------------------------------------------------
__global__ __launch_bounds__(256) void gemm_y_kernel(
    const float* __restrict__ X, const float* __restrict__ W)
{
    __shared__ float Xs[16][68];
    __shared__ float Ws[16][68];

    const int bm  = blockIdx.x * 64;
    const int bn  = blockIdx.y * 64;
    const int tid = threadIdx.x;
    const int tx  = tid & 15;
    const int ty  = tid >> 4;
    const int lk  = tid & 15;
    const int lr  = tid >> 4;

    float acc[4][4];
#pragma unroll
    for (int i = 0; i < 4; i++)
#pragma unroll
        for (int j = 0; j < 4; j++) acc[i][j] = 0.f;

    for (int k0 = 0; k0 < 256; k0 += 16) {
#pragma unroll
        for (int i = 0; i < 4; i++) {
            int m  = lr + i * 16;
            int gm = bm + m;
            Xs[lk][m] = (gm < N_IDENT) ? X[gm * 256 + k0 + lk] : 0.f;
            Ws[lk][m] = W[(bn + m) * 512 + k0 + lk];
        }
        __syncthreads();
#pragma unroll
        for (int k = 0; k < 16; k++) {
            float4 a = *(const float4*)(&Xs[k][ty * 4]);
            float4 b = *(const float4*)(&Ws[k][tx * 4]);
            float av[4] = {a.x, a.y, a.z, a.w};
            float bv[4] = {b.x, b.y, b.z, b.w};
#pragma unroll
            for (int i = 0; i < 4; i++)
#pragma unroll
                for (int j = 0; j < 4; j++) acc[i][j] += av[i] * bv[j];
        }
        __syncthreads();
    }

#pragma unroll
    for (int i = 0; i < 4; i++) {
        int gm = bm + ty * 4 + i;
        if (gm < N_IDENT) {
            float4 v = make_float4(acc[i][0], acc[i][1], acc[i][2], acc[i][3]);
            *(float4*)(&g_Y[gm * 256 + bn + tx * 4]) = v;
        }
    }
}

// ---------------------------------------------------------------------------
// All five tiny linear precomputes in ONE kernel.
// One WARP per output element (v, o): lanes stride k (coalesced W-row reads),
// butterfly reduce, lane 0 writes.
// Segments (warp-id ranges):
//   [0,      30720)  : g_Tid   = node_table[120,256] @ W_id  [:,256:512]^T + b_id
//   [30720,  61440)  : g_Tprim = node_table          @ W_prim[:, 64:320]^T + b_prim
//   [61440,  92160)  : g_Tmod  = node_table          @ W_mod [:, 64:320]^T + b_mod
//   [92160,  96256)  : g_P     = prim_table[16,64]   @ W_prim[:,  0: 64]^T
//   [96256, 100352)  : g_M     = mod_table [16,64]   @ W_mod [:,  0: 64]^T
// ---------------------------------------------------------------------------
#define PRE_WARPS 100352

__global__ __launch_bounds__(256) void precompute_kernel(
    const float* __restrict__ node_table,
    const float* __restrict__ prim_table,
    const float* __restrict__ mod_table,
    const float* __restrict__ W_id,   const float* __restrict__ b_id,
    const float* __restrict__ W_prim, const float* __restrict__ b_prim,
    const float* __restrict__ W_mod,  const float* __restrict__ b_mod)
{
    int w    = (blockIdx.x * 256 + threadIdx.x) >> 5;
    int lane = threadIdx.x & 31;
    if (w >= PRE_WARPS) return;

    const float* tbl;
    const float* wrow;
    const float* bias = nullptr;
    float* dst;
    int v, o, K;

    if (w < 92160) {
        int seg = w / 30720;          // 0,1,2
        int r   = w - seg * 30720;
        v = r >> 8;  o = r & 255;  K = 256;
        tbl = node_table + v * 256;
        if (seg == 0)      { wrow = W_id   + o * 512 + 256; bias = b_id;   dst = g_Tid;   }
        else if (seg == 1) { wrow = W_prim + o * 320 + 64;  bias = b_prim; dst = g_Tprim; }
        else               { wrow = W_mod  + o * 320 + 64;  bias = b_mod;  dst = g_Tmod;  }
    } else {
        int r = w - 92160;
        int seg = r >> 12;            // 0 -> P, 1 -> M
        r &= 4095;
        v = r >> 8;  o = r & 255;  K = 64;
        if (seg == 0) { tbl = prim_table + v * 64; wrow = W_prim + o * 320; dst = g_P; }
        else          { tbl = mod_table  + v * 64; wrow = W_mod  + o * 320; dst = g_M; }
    }

    float s = 0.f;
    for (int k = lane; k < K; k += 32)
        s += tbl[k] * wrow[k];
#pragma unroll
    for (int off = 16; off > 0; off >>= 1)
        s += __shfl_xor_sync(0xFFFFFFFFu, s, off);

    if (lane == 0) {
        if (bias) s += bias[o];
        dst[v * D + o] = s;
    }
}

__global__ void init_flags_kernel()
{
    int n = blockIdx.x * blockDim.x + threadIdx.x;
    if (n < N_NODES) g_flag[n] = -1;
}

__global__ void set_flags_kernel(
    const int* __restrict__ id_node, const int* __restrict__ prim_node,
    const int* __restrict__ mod_node)
{
    int i = blockIdx.x * blockDim.x + threadIdx.x;
    if (i < N_ID) {
        g_flag[id_node[i]] = i;                              // kind 0
    } else if (i < N_ID + N_PRIM) {
        int j = i - N_ID;
        g_flag[prim_node[j]] = (1 << 28) | j;                // kind 1
    } else if (i < N_ID + N_PRIM + N_MOD) {
        int j = i - N_ID - N_PRIM;
        g_flag[mod_node[j]] = (2 << 28) | j;                 // kind 2
    }
}

// ---------------------------------------------------------------------------
// One float4 per thread, 64 threads per node row.
// ---------------------------------------------------------------------------
__global__ __launch_bounds__(256) void finalize_kernel(
    const float4* __restrict__ tbl4,
    const int* __restrict__ types,
    const int* __restrict__ id_ident,
    const int* __restrict__ prim_types,
    const int* __restrict__ mod_ids,
    float4* __restrict__ out4)
{
    long long idx = (long long)blockIdx.x * 256 + threadIdx.x;
    int node = (int)(idx >> 6);
    int c    = (int)(idx & 63);
    if (node >= N_NODES) return;

    int f = g_flag[node];
    int t = types[node];
    float4 r;
    if (f < 0) {
        r = tbl4[t * 64 + c];
    } else {
        int kind = f >> 28;
        int row  = f & 0x0FFFFFFF;
        float4 x, y;
        if (kind == 0) {
            x = ((const float4*)g_Y)[(long long)id_ident[row] * 64 + c];
            y = ((const float4*)g_Tid)[t * 64 + c];
        } else if (kind == 1) {
            x = ((const float4*)g_P)[prim_types[row] * 64 + c];
            y = ((const float4*)g_Tprim)[t * 64 + c];
        } else {
            x = ((const float4*)g_M)[mod_ids[row] * 64 + c];
            y = ((const float4*)g_Tmod)[t * 64 + c];
        }
        r = make_float4(x.x + y.x, x.y + y.y, x.z + y.z, x.w + y.w);
    }
    out4[(long long)node * 64 + c] = r;
}

extern "C" void kernel_launch(void* const* d_in, const int* in_sizes, int n_in,
                              void* d_out, int out_size)
{
    const float* identifiers = (const float*)d_in[0];   // [50000, 256]
    const float* node_table  = (const float*)d_in[1];   // [120, 256]
    const float* prim_table  = (const float*)d_in[2];   // [16, 64]
    const float* mod_table   = (const float*)d_in[3];   // [16, 64]
    const float* W_id        = (const float*)d_in[4];   // [256, 512]
    const float* b_id        = (const float*)d_in[5];   // [256]
    const float* W_prim      = (const float*)d_in[6];   // [256, 320]
    const float* b_prim      = (const float*)d_in[7];   // [256]
    const float* W_mod       = (const float*)d_in[8];   // [256, 320]
    const float* b_mod       = (const float*)d_in[9];   // [256]
    const int*   types       = (const int*)d_in[10];    // [500000]
    const int*   id_ident    = (const int*)d_in[11];    // [150000]
    const int*   id_node     = (const int*)d_in[12];    // [150000]
    const int*   prim_types  = (const int*)d_in[13];    // [60000]
    const int*   prim_node   = (const int*)d_in[14];    // [60000]
    const int*   mod_ids     = (const int*)d_in[15];    // [30000]
    const int*   mod_node    = (const int*)d_in[16];    // [30000]
    float*       out         = (float*)d_out;

    // Flags: inverse map node -> (kind, leaf row)
    init_flags_kernel<<<(N_NODES + 255) / 256, 256>>>();
    {
        int total = N_ID + N_PRIM + N_MOD;
        set_flags_kernel<<<(total + 255) / 256, 256>>>(id_node, prim_node, mod_node);
    }

    // All tiny precomputes in one launch (warp per output, coalesced k)
    {
        int blocks = (PRE_WARPS * 32 + 255) / 256;
        precompute_kernel<<<blocks, 256>>>(node_table, prim_table, mod_table,
                                           W_id, b_id, W_prim, b_prim, W_mod, b_mod);
    }

    // Main GEMM: Y = identifiers @ W_id[:, :256]^T
    {
        dim3 grid((N_IDENT + 63) / 64, 256 / 64);
        gemm_y_kernel<<<grid, 256>>>(identifiers, W_id);
    }

    // Fused output pass
    {
        long long total = (long long)N_NODES * 64;
        int blocks = (int)((total + 255) / 256);
        finalize_kernel<<<blocks, 256>>>(
            (const float4*)node_table, types, id_ident, prim_types, mod_ids,
            (float4*)out);
    }
}

// round 4
// speedup vs baseline: 1.8699x; 1.4586x over previous
#include <cuda_runtime.h>
#include <cstdint>

#define N_NODES    500000
#define D          256
#define N_IDENT    50000
#define N_ID       150000
#define N_PRIM     60000
#define N_MOD      30000
#define NT_VOCAB   120
#define PV         16
#define MV         16

// Scratch (allocation-free rule: __device__ globals)
__device__ float g_Y[N_IDENT * D];
__device__ float g_Tid[NT_VOCAB * D];
__device__ float g_Tprim[NT_VOCAB * D];
__device__ float g_Tmod[NT_VOCAB * D];
__device__ float g_P[PV * D];
__device__ float g_M[MV * D];
__device__ int   g_flag[N_NODES];

__device__ __forceinline__ uint32_t f2tf32(float f) {
    uint32_t u;
    asm("cvt.rna.tf32.f32 %0, %1;" : "=r"(u) : "f"(f));
    return u;
}

// ---------------------------------------------------------------------------
// Y[50000, 256] = X[50000, 256] @ W_id[:, :256]^T  via mma.sync tf32 (HMMA).
// CTA tile 128x128, BK=32, 8 warps (4 M x 2 N), warp tile 32x64.
// mma.m16n8k8.row.col: A row-major [m][k], B col-major == W rows [n][k].
// ---------------------------------------------------------------------------
#define BM 128
#define BN 128
#define BK 32
#define PADK 40   // words per SMEM row (160B: 16B-aligned, conflict-free STS.128 phases)

__global__ __launch_bounds__(256) void gemm_mma_kernel(
    const float* __restrict__ X, const float* __restrict__ W)
{
    __shared__ uint32_t As[BM][PADK];   // 20 KB
    __shared__ uint32_t Bs[BN][PADK];   // 20 KB

    const int tid    = threadIdx.x;
    const int wid    = tid >> 5;
    const int lane   = tid & 31;
    const int g      = lane >> 2;       // group id (row within 8)
    const int tg     = lane & 3;        // thread in group (k / col pairs)
    const int warp_m = wid & 3;         // 0..3
    const int warp_n = wid >> 2;        // 0..1
    const int bm     = blockIdx.x * BM;
    const int bn     = blockIdx.y * BN;

    float acc[2][8][4];
#pragma unroll
    for (int mt = 0; mt < 2; mt++)
#pragma unroll
        for (int nt = 0; nt < 8; nt++)
#pragma unroll
            for (int i = 0; i < 4; i++) acc[mt][nt][i] = 0.f;

    for (int k0 = 0; k0 < 256; k0 += BK) {
        // Stage A tile: 128 rows x 32 k (tf32-converted), coalesced float4 loads
#pragma unroll
        for (int i = 0; i < 4; i++) {
            int idx4 = tid + i * 256;          // 0..1023
            int m  = idx4 >> 3;
            int c4 = idx4 & 7;
            float4 v = make_float4(0.f, 0.f, 0.f, 0.f);
            if (bm + m < N_IDENT)
                v = *(const float4*)(X + (size_t)(bm + m) * 256 + k0 + c4 * 4);
            uint4 t = make_uint4(f2tf32(v.x), f2tf32(v.y), f2tf32(v.z), f2tf32(v.w));
            *(uint4*)&As[m][c4 * 4] = t;
        }
        // Stage B tile: 128 n-rows x 32 k of W[n*512 + k]
#pragma unroll
        for (int i = 0; i < 4; i++) {
            int idx4 = tid + i * 256;
            int n  = idx4 >> 3;
            int c4 = idx4 & 7;
            float4 v = *(const float4*)(W + (size_t)(bn + n) * 512 + k0 + c4 * 4);
            uint4 t = make_uint4(f2tf32(v.x), f2tf32(v.y), f2tf32(v.z), f2tf32(v.w));
            *(uint4*)&Bs[n][c4 * 4] = t;
        }
        __syncthreads();

#pragma unroll
        for (int kk = 0; kk < BK; kk += 8) {
            uint32_t a[2][4];
#pragma unroll
            for (int mt = 0; mt < 2; mt++) {
                int row = warp_m * 32 + mt * 16;
                a[mt][0] = As[row + g][kk + tg];
                a[mt][1] = As[row + g + 8][kk + tg];
                a[mt][2] = As[row + g][kk + tg + 4];
                a[mt][3] = As[row + g + 8][kk + tg + 4];
            }
#pragma unroll
            for (int nt = 0; nt < 8; nt++) {
                int col = warp_n * 64 + nt * 8;
                uint32_t b0 = Bs[col + g][kk + tg];
                uint32_t b1 = Bs[col + g][kk + tg + 4];
#pragma unroll
                for (int mt = 0; mt < 2; mt++) {
                    asm volatile(
                        "mma.sync.aligned.m16n8k8.row.col.f32.tf32.tf32.f32 "
                        "{%0,%1,%2,%3}, {%4,%5,%6,%7}, {%8,%9}, {%0,%1,%2,%3};"
                        : "+f"(acc[mt][nt][0]), "+f"(acc[mt][nt][1]),
                          "+f"(acc[mt][nt][2]), "+f"(acc[mt][nt][3])
                        : "r"(a[mt][0]), "r"(a[mt][1]), "r"(a[mt][2]), "r"(a[mt][3]),
                          "r"(b0), "r"(b1));
                }
            }
        }
        __syncthreads();
    }

    // Epilogue: float2 stores, coalesced 32B sectors per row
#pragma unroll
    for (int mt = 0; mt < 2; mt++) {
        int row0 = bm + warp_m * 32 + mt * 16 + g;
#pragma unroll
        for (int nt = 0; nt < 8; nt++) {
            int col = bn + warp_n * 64 + nt * 8 + tg * 2;
            if (row0 < N_IDENT)
                *(float2*)&g_Y[(size_t)row0 * 256 + col] =
                    make_float2(acc[mt][nt][0], acc[mt][nt][1]);
            if (row0 + 8 < N_IDENT)
                *(float2*)&g_Y[(size_t)(row0 + 8) * 256 + col] =
                    make_float2(acc[mt][nt][2], acc[mt][nt][3]);
        }
    }
}

// ---------------------------------------------------------------------------
// All five tiny linear precomputes in ONE kernel (warp per output element).
// ---------------------------------------------------------------------------
#define PRE_WARPS 100352

__global__ __launch_bounds__(256) void precompute_kernel(
    const float* __restrict__ node_table,
    const float* __restrict__ prim_table,
    const float* __restrict__ mod_table,
    const float* __restrict__ W_id,   const float* __restrict__ b_id,
    const float* __restrict__ W_prim, const float* __restrict__ b_prim,
    const float* __restrict__ W_mod,  const float* __restrict__ b_mod)
{
    int w    = (blockIdx.x * 256 + threadIdx.x) >> 5;
    int lane = threadIdx.x & 31;
    if (w >= PRE_WARPS) return;

    const float* tbl;
    const float* wrow;
    const float* bias = nullptr;
    float* dst;
    int v, o, K;

    if (w < 92160) {
        int seg = w / 30720;
        int r   = w - seg * 30720;
        v = r >> 8;  o = r & 255;  K = 256;
        tbl = node_table + v * 256;
        if (seg == 0)      { wrow = W_id   + o * 512 + 256; bias = b_id;   dst = g_Tid;   }
        else if (seg == 1) { wrow = W_prim + o * 320 + 64;  bias = b_prim; dst = g_Tprim; }
        else               { wrow = W_mod  + o * 320 + 64;  bias = b_mod;  dst = g_Tmod;  }
    } else {
        int r = w - 92160;
        int seg = r >> 12;
        r &= 4095;
        v = r >> 8;  o = r & 255;  K = 64;
        if (seg == 0) { tbl = prim_table + v * 64; wrow = W_prim + o * 320; dst = g_P; }
        else          { tbl = mod_table  + v * 64; wrow = W_mod  + o * 320; dst = g_M; }
    }

    float s = 0.f;
    for (int k = lane; k < K; k += 32)
        s += tbl[k] * wrow[k];
#pragma unroll
    for (int off = 16; off > 0; off >>= 1)
        s += __shfl_xor_sync(0xFFFFFFFFu, s, off);

    if (lane == 0) {
        if (bias) s += bias[o];
        dst[v * D + o] = s;
    }
}

__global__ void init_flags_kernel()
{
    int n = blockIdx.x * blockDim.x + threadIdx.x;
    if (n < N_NODES) g_flag[n] = -1;
}

__global__ void set_flags_kernel(
    const int* __restrict__ id_node, const int* __restrict__ prim_node,
    const int* __restrict__ mod_node)
{
    int i = blockIdx.x * blockDim.x + threadIdx.x;
    if (i < N_ID) {
        g_flag[id_node[i]] = i;
    } else if (i < N_ID + N_PRIM) {
        int j = i - N_ID;
        g_flag[prim_node[j]] = (1 << 28) | j;
    } else if (i < N_ID + N_PRIM + N_MOD) {
        int j = i - N_ID - N_PRIM;
        g_flag[mod_node[j]] = (2 << 28) | j;
    }
}

// ---------------------------------------------------------------------------
// One float4 per thread, 64 threads per node row.
// ---------------------------------------------------------------------------
__global__ __launch_bounds__(256) void finalize_kernel(
    const float4* __restrict__ tbl4,
    const int* __restrict__ types,
    const int* __restrict__ id_ident,
    const int* __restrict__ prim_types,
    const int* __restrict__ mod_ids,
    float4* __restrict__ out4)
{
    long long idx = (long long)blockIdx.x * 256 + threadIdx.x;
    int node = (int)(idx >> 6);
    int c    = (int)(idx & 63);
    if (node >= N_NODES) return;

    int f = g_flag[node];
    int t = types[node];
    float4 r;
    if (f < 0) {
        r = tbl4[t * 64 + c];
    } else {
        int kind = f >> 28;
        int row  = f & 0x0FFFFFFF;
        float4 x, y;
        if (kind == 0) {
            x = ((const float4*)g_Y)[(long long)id_ident[row] * 64 + c];
            y = ((const float4*)g_Tid)[t * 64 + c];
        } else if (kind == 1) {
            x = ((const float4*)g_P)[prim_types[row] * 64 + c];
            y = ((const float4*)g_Tprim)[t * 64 + c];
        } else {
            x = ((const float4*)g_M)[mod_ids[row] * 64 + c];
            y = ((const float4*)g_Tmod)[t * 64 + c];
        }
        r = make_float4(x.x + y.x, x.y + y.y, x.z + y.z, x.w + y.w);
    }
    out4[(long long)node * 64 + c] = r;
}

extern "C" void kernel_launch(void* const* d_in, const int* in_sizes, int n_in,
                              void* d_out, int out_size)
{
    const float* identifiers = (const float*)d_in[0];
    const float* node_table  = (const float*)d_in[1];
    const float* prim_table  = (const float*)d_in[2];
    const float* mod_table   = (const float*)d_in[3];
    const float* W_id        = (const float*)d_in[4];
    const float* b_id        = (const float*)d_in[5];
    const float* W_prim      = (const float*)d_in[6];
    const float* b_prim      = (const float*)d_in[7];
    const float* W_mod       = (const float*)d_in[8];
    const float* b_mod       = (const float*)d_in[9];
    const int*   types       = (const int*)d_in[10];
    const int*   id_ident    = (const int*)d_in[11];
    const int*   id_node     = (const int*)d_in[12];
    const int*   prim_types  = (const int*)d_in[13];
    const int*   prim_node   = (const int*)d_in[14];
    const int*   mod_ids     = (const int*)d_in[15];
    const int*   mod_node    = (const int*)d_in[16];
    float*       out         = (float*)d_out;

    // Flags: inverse map node -> (kind, leaf row)
    init_flags_kernel<<<(N_NODES + 255) / 256, 256>>>();
    {
        int total = N_ID + N_PRIM + N_MOD;
        set_flags_kernel<<<(total + 255) / 256, 256>>>(id_node, prim_node, mod_node);
    }

    // Tiny precomputes (one launch)
    {
        int blocks = (PRE_WARPS * 32 + 255) / 256;
        precompute_kernel<<<blocks, 256>>>(node_table, prim_table, mod_table,
                                           W_id, b_id, W_prim, b_prim, W_mod, b_mod);
    }

    // Main GEMM on HMMA tf32: Y = identifiers @ W_id[:, :256]^T
    {
        dim3 grid((N_IDENT + BM - 1) / BM, 256 / BN);   // 391 x 2
        gemm_mma_kernel<<<grid, 256>>>(identifiers, W_id);
    }

    // Fused output pass
    {
        long long total = (long long)N_NODES * 64;
        int blocks = (int)((total + 255) / 256);
        finalize_kernel<<<blocks, 256>>>(
            (const float4*)node_table, types, id_ident, prim_types, mod_ids,
            (float4*)out);
    }
}

// round 5
// speedup vs baseline: 2.0727x; 1.1084x over previous
#include <cuda_runtime.h>
#include <cstdint>

#define N_NODES    500000
#define D          256
#define N_IDENT    50000
#define N_ID       150000
#define N_PRIM     60000
#define N_MOD      30000
#define NT_VOCAB   120
#define PV         16
#define MV         16

// Scratch (allocation-free rule: __device__ globals)
__device__ float g_Y[N_IDENT * D];
__device__ float g_Tid[NT_VOCAB * D];
__device__ float g_Tprim[NT_VOCAB * D];
__device__ float g_Tmod[NT_VOCAB * D];
__device__ float g_P[PV * D];
__device__ float g_M[MV * D];
__device__ int   g_flag[N_NODES];

// ---------------------------------------------------------------------------
// Y[50000, 256] = X[50000, 256] @ W_id[:, :256]^T  via mma.sync tf32 (HMMA),
// cp.async double-buffered. CTA tile 128x128, BK=32, 8 warps (4M x 2N).
// fp32 bits fed directly to tf32 mma (HW truncates mantissa).
// ---------------------------------------------------------------------------
#define BM 128
#define BN 128
#define BK 32
#define PADK 36                     // words per SMEM row: 144B, 16B aligned, (4g+tg)%32 conflict-free
#define AW (BM * PADK)              // words per A tile = 4608
#define BUFW (2 * AW)               // words per buffer (A + B) = 9216
#define GEMM_SMEM_BYTES (2 * BUFW * 4)   // 73728

__device__ __forceinline__ uint32_t smem_u32(const void* p) {
    uint32_t a;
    asm("{ .reg .u64 t; cvta.to.shared.u64 t, %1; cvt.u32.u64 %0, t; }"
        : "=r"(a) : "l"(p));
    return a;
}
__device__ __forceinline__ void cp_async16(uint32_t dst, const void* src, uint32_t src_bytes) {
    asm volatile("cp.async.cg.shared.global [%0], [%1], 16, %2;"
                 :: "r"(dst), "l"(src), "r"(src_bytes) : "memory");
}
__device__ __forceinline__ void cp_commit() {
    asm volatile("cp.async.commit_group;" ::: "memory");
}
template <int N>
__device__ __forceinline__ void cp_wait() {
    asm volatile("cp.async.wait_group %0;" :: "n"(N) : "memory");
}

__global__ __launch_bounds__(256) void gemm_mma_kernel(
    const float* __restrict__ X, const float* __restrict__ W)
{
    extern __shared__ uint32_t smem[];

    const int tid    = threadIdx.x;
    const int wid    = tid >> 5;
    const int lane   = tid & 31;
    const int g      = lane >> 2;
    const int tg     = lane & 3;
    const int warp_m = wid & 3;
    const int warp_n = wid >> 2;
    const int bm     = blockIdx.x * BM;
    const int bn     = blockIdx.y * BN;

    const uint32_t smem_base = smem_u32(smem);

    // Per-thread staging coords (4 float4s each for A and B)
    const int m_  = tid >> 3;            // row when idx4 = tid (i=0 base); full set via +32 rows
    const int c4_ = tid & 7;

    float acc[2][8][4];
#pragma unroll
    for (int mt = 0; mt < 2; mt++)
#pragma unroll
        for (int nt = 0; nt < 8; nt++)
#pragma unroll
            for (int i = 0; i < 4; i++) acc[mt][nt][i] = 0.f;

    auto issue_loads = [&](int chunk, int buf) {
        const int k0 = chunk * BK;
        const uint32_t abase = smem_base + (buf * BUFW) * 4;
        const uint32_t bbase = abase + AW * 4;
#pragma unroll
        for (int i = 0; i < 4; i++) {
            int m  = m_ + i * 32;
            int gm = bm + m;
            uint32_t dst = abase + (m * PADK + c4_ * 4) * 4;
            const float* src = X + (size_t)gm * 256 + k0 + c4_ * 4;
            cp_async16(dst, src, (gm < N_IDENT) ? 16u : 0u);
        }
#pragma unroll
        for (int i = 0; i < 4; i++) {
            int n = m_ + i * 32;
            uint32_t dst = bbase + (n * PADK + c4_ * 4) * 4;
            const float* src = W + (size_t)(bn + n) * 512 + k0 + c4_ * 4;
            cp_async16(dst, src, 16u);
        }
        cp_commit();
    };

    issue_loads(0, 0);

    for (int chunk = 0; chunk < 8; chunk++) {
        if (chunk + 1 < 8) {
            issue_loads(chunk + 1, (chunk + 1) & 1);
            cp_wait<1>();
        } else {
            cp_wait<0>();
        }
        __syncthreads();

        const int buf = chunk & 1;
        const uint32_t* As = smem + buf * BUFW;
        const uint32_t* Bs = As + AW;

#pragma unroll
        for (int kk = 0; kk < BK; kk += 8) {
            uint32_t a[2][4];
#pragma unroll
            for (int mt = 0; mt < 2; mt++) {
                int row = warp_m * 32 + mt * 16;
                a[mt][0] = As[(row + g)     * PADK + kk + tg];
                a[mt][1] = As[(row + g + 8) * PADK + kk + tg];
                a[mt][2] = As[(row + g)     * PADK + kk + tg + 4];
                a[mt][3] = As[(row + g + 8) * PADK + kk + tg + 4];
            }
#pragma unroll
            for (int nt = 0; nt < 8; nt++) {
                int col = warp_n * 64 + nt * 8;
                uint32_t b0 = Bs[(col + g) * PADK + kk + tg];
                uint32_t b1 = Bs[(col + g) * PADK + kk + tg + 4];
#pragma unroll
                for (int mt = 0; mt < 2; mt++) {
                    asm volatile(
                        "mma.sync.aligned.m16n8k8.row.col.f32.tf32.tf32.f32 "
                        "{%0,%1,%2,%3}, {%4,%5,%6,%7}, {%8,%9}, {%0,%1,%2,%3};"
                        : "+f"(acc[mt][nt][0]), "+f"(acc[mt][nt][1]),
                          "+f"(acc[mt][nt][2]), "+f"(acc[mt][nt][3])
                        : "r"(a[mt][0]), "r"(a[mt][1]), "r"(a[mt][2]), "r"(a[mt][3]),
                          "r"(b0), "r"(b1));
                }
            }
        }
        __syncthreads();
    }

    // Epilogue: float2 stores (natural m16n8 accumulator layout)
#pragma unroll
    for (int mt = 0; mt < 2; mt++) {
        int row0 = bm + warp_m * 32 + mt * 16 + g;
#pragma unroll
        for (int nt = 0; nt < 8; nt++) {
            int col = bn + warp_n * 64 + nt * 8 + tg * 2;
            if (row0 < N_IDENT)
                *(float2*)&g_Y[(size_t)row0 * 256 + col] =
                    make_float2(acc[mt][nt][0], acc[mt][nt][1]);
            if (row0 + 8 < N_IDENT)
                *(float2*)&g_Y[(size_t)(row0 + 8) * 256 + col] =
                    make_float2(acc[mt][nt][2], acc[mt][nt][3]);
        }
    }
}

// ---------------------------------------------------------------------------
// Five tiny linear precomputes + flag-array init fused into ONE kernel.
// Blocks [0, PRE_BLOCKS): warp per output element. Blocks beyond: flag init.
// ---------------------------------------------------------------------------
#define PRE_WARPS  100352
#define PRE_BLOCKS ((PRE_WARPS * 32 + 255) / 256)       // 12544
#define FLAG_BLOCKS ((N_NODES + 255) / 256)             // 1954

__global__ __launch_bounds__(256) void precompute_kernel(
    const float* __restrict__ node_table,
    const float* __restrict__ prim_table,
    const float* __restrict__ mod_table,
    const float* __restrict__ W_id,   const float* __restrict__ b_id,
    const float* __restrict__ W_prim, const float* __restrict__ b_prim,
    const float* __restrict__ W_mod,  const float* __restrict__ b_mod)
{
    if (blockIdx.x >= PRE_BLOCKS) {
        int n = (blockIdx.x - PRE_BLOCKS) * 256 + threadIdx.x;
        if (n < N_NODES) g_flag[n] = -1;
        return;
    }

    int w    = (blockIdx.x * 256 + threadIdx.x) >> 5;
    int lane = threadIdx.x & 31;
    if (w >= PRE_WARPS) return;

    const float* tbl;
    const float* wrow;
    const float* bias = nullptr;
    float* dst;
    int v, o, K;

    if (w < 92160) {
        int seg = w / 30720;
        int r   = w - seg * 30720;
        v = r >> 8;  o = r & 255;  K = 256;
        tbl = node_table + v * 256;
        if (seg == 0)      { wrow = W_id   + o * 512 + 256; bias = b_id;   dst = g_Tid;   }
        else if (seg == 1) { wrow = W_prim + o * 320 + 64;  bias = b_prim; dst = g_Tprim; }
        else               { wrow = W_mod  + o * 320 + 64;  bias = b_mod;  dst = g_Tmod;  }
    } else {
        int r = w - 92160;
        int seg = r >> 12;
        r &= 4095;
        v = r >> 8;  o = r & 255;  K = 64;
        if (seg == 0) { tbl = prim_table + v * 64; wrow = W_prim + o * 320; dst = g_P; }
        else          { tbl = mod_table  + v * 64; wrow = W_mod  + o * 320; dst = g_M; }
    }

    float s = 0.f;
    for (int k = lane; k < K; k += 32)
        s += tbl[k] * wrow[k];
#pragma unroll
    for (int off = 16; off > 0; off >>= 1)
        s += __shfl_xor_sync(0xFFFFFFFFu, s, off);

    if (lane == 0) {
        if (bias) s += bias[o];
        dst[v * D + o] = s;
    }
}

__global__ void set_flags_kernel(
    const int* __restrict__ id_node, const int* __restrict__ prim_node,
    const int* __restrict__ mod_node)
{
    int i = blockIdx.x * blockDim.x + threadIdx.x;
    if (i < N_ID) {
        g_flag[id_node[i]] = i;
    } else if (i < N_ID + N_PRIM) {
        int j = i - N_ID;
        g_flag[prim_node[j]] = (1 << 28) | j;
    } else if (i < N_ID + N_PRIM + N_MOD) {
        int j = i - N_ID - N_PRIM;
        g_flag[mod_node[j]] = (2 << 28) | j;
    }
}

// ---------------------------------------------------------------------------
// One float4 per thread, 64 threads per node row.
// ---------------------------------------------------------------------------
__global__ __launch_bounds__(256) void finalize_kernel(
    const float4* __restrict__ tbl4,
    const int* __restrict__ types,
    const int* __restrict__ id_ident,
    const int* __restrict__ prim_types,
    const int* __restrict__ mod_ids,
    float4* __restrict__ out4)
{
    long long idx = (long long)blockIdx.x * 256 + threadIdx.x;
    int node = (int)(idx >> 6);
    int c    = (int)(idx & 63);
    if (node >= N_NODES) return;

    int f = g_flag[node];
    int t = types[node];
    float4 r;
    if (f < 0) {
        r = tbl4[t * 64 + c];
    } else {
        int kind = f >> 28;
        int row  = f & 0x0FFFFFFF;
        float4 x, y;
        if (kind == 0) {
            x = ((const float4*)g_Y)[(long long)id_ident[row] * 64 + c];
            y = ((const float4*)g_Tid)[t * 64 + c];
        } else if (kind == 1) {
            x = ((const float4*)g_P)[prim_types[row] * 64 + c];
            y = ((const float4*)g_Tprim)[t * 64 + c];
        } else {
            x = ((const float4*)g_M)[mod_ids[row] * 64 + c];
            y = ((const float4*)g_Tmod)[t * 64 + c];
        }
        r = make_float4(x.x + y.x, x.y + y.y, x.z + y.z, x.w + y.w);
    }
    out4[(long long)node * 64 + c] = r;
}

extern "C" void kernel_launch(void* const* d_in, const int* in_sizes, int n_in,
                              void* d_out, int out_size)
{
    const float* identifiers = (const float*)d_in[0];
    const float* node_table  = (const float*)d_in[1];
    const float* prim_table  = (const float*)d_in[2];
    const float* mod_table   = (const float*)d_in[3];
    const float* W_id        = (const float*)d_in[4];
    const float* b_id        = (const float*)d_in[5];
    const float* W_prim      = (const float*)d_in[6];
    const float* b_prim      = (const float*)d_in[7];
    const float* W_mod       = (const float*)d_in[8];
    const float* b_mod       = (const float*)d_in[9];
    const int*   types       = (const int*)d_in[10];
    const int*   id_ident    = (const int*)d_in[11];
    const int*   id_node     = (const int*)d_in[12];
    const int*   prim_types  = (const int*)d_in[13];
    const int*   prim_node   = (const int*)d_in[14];
    const int*   mod_ids     = (const int*)d_in[15];
    const int*   mod_node    = (const int*)d_in[16];
    float*       out         = (float*)d_out;

    static bool attr_set = false;
    if (!attr_set) {
        cudaFuncSetAttribute(gemm_mma_kernel,
                             cudaFuncAttributeMaxDynamicSharedMemorySize,
                             GEMM_SMEM_BYTES);
        attr_set = true;
    }

    // Precomputes + flag init (one launch)
    precompute_kernel<<<PRE_BLOCKS + FLAG_BLOCKS, 256>>>(
        node_table, prim_table, mod_table,
        W_id, b_id, W_prim, b_prim, W_mod, b_mod);

    // Flags: scatter leaf kinds (after init)
    {
        int total = N_ID + N_PRIM + N_MOD;
        set_flags_kernel<<<(total + 255) / 256, 256>>>(id_node, prim_node, mod_node);
    }

    // Main GEMM on HMMA tf32 + cp.async pipeline
    {
        dim3 grid((N_IDENT + BM - 1) / BM, 256 / BN);   // 391 x 2
        gemm_mma_kernel<<<grid, 256, GEMM_SMEM_BYTES>>>(identifiers, W_id);
    }

    // Fused output pass
    {
        long long total = (long long)N_NODES * 64;
        int blocks = (int)((total + 255) / 256);
        finalize_kernel<<<blocks, 256>>>(
            (const float4*)node_table, types, id_ident, prim_types, mod_ids,
            (float4*)out);
    }
}

// round 6
// speedup vs baseline: 2.6767x; 1.2914x over previous
#include <cuda_runtime.h>
#include <cstdint>

#define N_NODES    500000
#define D          256
#define N_IDENT    50000
#define N_ID       150000
#define N_PRIM     60000
#define N_MOD      30000
#define NT_VOCAB   120
#define PV         16
#define MV         16

// Scratch (allocation-free rule: __device__ globals)
__device__ float g_Y[N_IDENT * D];
__device__ float g_Tid[NT_VOCAB * D];
__device__ float g_Tprim[NT_VOCAB * D];
__device__ float g_Tmod[NT_VOCAB * D];
__device__ float g_P[PV * D];
__device__ float g_M[MV * D];
__device__ int   g_flag[N_NODES];

// ---------------------------------------------------------------------------
// Y[50000, 256] = X[50000, 256] @ W_id[:, :256]^T  via mma.sync tf32 (HMMA),
// cp.async double-buffered. CTA tile 128x128, BK=32, 8 warps (4M x 2N).
// ---------------------------------------------------------------------------
#define BM 128
#define BN 128
#define BK 32
#define PADK 36
#define AW (BM * PADK)
#define BUFW (2 * AW)
#define GEMM_SMEM_BYTES (2 * BUFW * 4)   // 73728

__device__ __forceinline__ uint32_t smem_u32(const void* p) {
    uint32_t a;
    asm("{ .reg .u64 t; cvta.to.shared.u64 t, %1; cvt.u32.u64 %0, t; }"
        : "=r"(a) : "l"(p));
    return a;
}
__device__ __forceinline__ void cp_async16(uint32_t dst, const void* src, uint32_t src_bytes) {
    asm volatile("cp.async.cg.shared.global [%0], [%1], 16, %2;"
                 :: "r"(dst), "l"(src), "r"(src_bytes) : "memory");
}
__device__ __forceinline__ void cp_commit() {
    asm volatile("cp.async.commit_group;" ::: "memory");
}
template <int N>
__device__ __forceinline__ void cp_wait() {
    asm volatile("cp.async.wait_group %0;" :: "n"(N) : "memory");
}

__global__ __launch_bounds__(256) void gemm_mma_kernel(
    const float* __restrict__ X, const float* __restrict__ W)
{
    extern __shared__ uint32_t smem[];

    const int tid    = threadIdx.x;
    const int wid    = tid >> 5;
    const int lane   = tid & 31;
    const int g      = lane >> 2;
    const int tg     = lane & 3;
    const int warp_m = wid & 3;
    const int warp_n = wid >> 2;
    const int bm     = blockIdx.x * BM;
    const int bn     = blockIdx.y * BN;

    const uint32_t smem_base = smem_u32(smem);
    const int m_  = tid >> 3;
    const int c4_ = tid & 7;

    float acc[2][8][4];
#pragma unroll
    for (int mt = 0; mt < 2; mt++)
#pragma unroll
        for (int nt = 0; nt < 8; nt++)
#pragma unroll
            for (int i = 0; i < 4; i++) acc[mt][nt][i] = 0.f;

    auto issue_loads = [&](int chunk, int buf) {
        const int k0 = chunk * BK;
        const uint32_t abase = smem_base + (buf * BUFW) * 4;
        const uint32_t bbase = abase + AW * 4;
#pragma unroll
        for (int i = 0; i < 4; i++) {
            int m  = m_ + i * 32;
            int gm = bm + m;
            uint32_t dst = abase + (m * PADK + c4_ * 4) * 4;
            const float* src = X + (size_t)gm * 256 + k0 + c4_ * 4;
            cp_async16(dst, src, (gm < N_IDENT) ? 16u : 0u);
        }
#pragma unroll
        for (int i = 0; i < 4; i++) {
            int n = m_ + i * 32;
            uint32_t dst = bbase + (n * PADK + c4_ * 4) * 4;
            const float* src = W + (size_t)(bn + n) * 512 + k0 + c4_ * 4;
            cp_async16(dst, src, 16u);
        }
        cp_commit();
    };

    issue_loads(0, 0);

    for (int chunk = 0; chunk < 8; chunk++) {
        if (chunk + 1 < 8) {
            issue_loads(chunk + 1, (chunk + 1) & 1);
            cp_wait<1>();
        } else {
            cp_wait<0>();
        }
        __syncthreads();

        const int buf = chunk & 1;
        const uint32_t* As = smem + buf * BUFW;
        const uint32_t* Bs = As + AW;

#pragma unroll
        for (int kk = 0; kk < BK; kk += 8) {
            uint32_t a[2][4];
#pragma unroll
            for (int mt = 0; mt < 2; mt++) {
                int row = warp_m * 32 + mt * 16;
                a[mt][0] = As[(row + g)     * PADK + kk + tg];
                a[mt][1] = As[(row + g + 8) * PADK + kk + tg];
                a[mt][2] = As[(row + g)     * PADK + kk + tg + 4];
                a[mt][3] = As[(row + g + 8) * PADK + kk + tg + 4];
            }
#pragma unroll
            for (int nt = 0; nt < 8; nt++) {
                int col = warp_n * 64 + nt * 8;
                uint32_t b0 = Bs[(col + g) * PADK + kk + tg];
                uint32_t b1 = Bs[(col + g) * PADK + kk + tg + 4];
#pragma unroll
                for (int mt = 0; mt < 2; mt++) {
                    asm volatile(
                        "mma.sync.aligned.m16n8k8.row.col.f32.tf32.tf32.f32 "
                        "{%0,%1,%2,%3}, {%4,%5,%6,%7}, {%8,%9}, {%0,%1,%2,%3};"
                        : "+f"(acc[mt][nt][0]), "+f"(acc[mt][nt][1]),
                          "+f"(acc[mt][nt][2]), "+f"(acc[mt][nt][3])
                        : "r"(a[mt][0]), "r"(a[mt][1]), "r"(a[mt][2]), "r"(a[mt][3]),
                          "r"(b0), "r"(b1));
                }
            }
        }
        __syncthreads();
    }

#pragma unroll
    for (int mt = 0; mt < 2; mt++) {
        int row0 = bm + warp_m * 32 + mt * 16 + g;
#pragma unroll
        for (int nt = 0; nt < 8; nt++) {
            int col = bn + warp_n * 64 + nt * 8 + tg * 2;
            if (row0 < N_IDENT)
                *(float2*)&g_Y[(size_t)row0 * 256 + col] =
                    make_float2(acc[mt][nt][0], acc[mt][nt][1]);
            if (row0 + 8 < N_IDENT)
                *(float2*)&g_Y[(size_t)(row0 + 8) * 256 + col] =
                    make_float2(acc[mt][nt][2], acc[mt][nt][3]);
        }
    }
}

// ---------------------------------------------------------------------------
// Five tiny linear precomputes + flag-array init fused into ONE kernel.
// ---------------------------------------------------------------------------
#define PRE_WARPS  100352
#define PRE_BLOCKS ((PRE_WARPS * 32 + 255) / 256)
#define FLAG_BLOCKS ((N_NODES + 255) / 256)

__global__ __launch_bounds__(256) void precompute_kernel(
    const float* __restrict__ node_table,
    const float* __restrict__ prim_table,
    const float* __restrict__ mod_table,
    const float* __restrict__ W_id,   const float* __restrict__ b_id,
    const float* __restrict__ W_prim, const float* __restrict__ b_prim,
    const float* __restrict__ W_mod,  const float* __restrict__ b_mod)
{
    if (blockIdx.x >= PRE_BLOCKS) {
        int n = (blockIdx.x - PRE_BLOCKS) * 256 + threadIdx.x;
        if (n < N_NODES) g_flag[n] = -1;
        return;
    }

    int w    = (blockIdx.x * 256 + threadIdx.x) >> 5;
    int lane = threadIdx.x & 31;
    if (w >= PRE_WARPS) return;

    const float* tbl;
    const float* wrow;
    const float* bias = nullptr;
    float* dst;
    int v, o, K;

    if (w < 92160) {
        int seg = w / 30720;
        int r   = w - seg * 30720;
        v = r >> 8;  o = r & 255;  K = 256;
        tbl = node_table + v * 256;
        if (seg == 0)      { wrow = W_id   + o * 512 + 256; bias = b_id;   dst = g_Tid;   }
        else if (seg == 1) { wrow = W_prim + o * 320 + 64;  bias = b_prim; dst = g_Tprim; }
        else               { wrow = W_mod  + o * 320 + 64;  bias = b_mod;  dst = g_Tmod;  }
    } else {
        int r = w - 92160;
        int seg = r >> 12;
        r &= 4095;
        v = r >> 8;  o = r & 255;  K = 64;
        if (seg == 0) { tbl = prim_table + v * 64; wrow = W_prim + o * 320; dst = g_P; }
        else          { tbl = mod_table  + v * 64; wrow = W_mod  + o * 320; dst = g_M; }
    }

    float s = 0.f;
    for (int k = lane; k < K; k += 32)
        s += tbl[k] * wrow[k];
#pragma unroll
    for (int off = 16; off > 0; off >>= 1)
        s += __shfl_xor_sync(0xFFFFFFFFu, s, off);

    if (lane == 0) {
        if (bias) s += bias[o];
        dst[v * D + o] = s;
    }
}

// ---------------------------------------------------------------------------
// Scatter RESOLVED source rows into flags: finalize needs no index arrays.
//   kind 0 (id):   src = id_ident[i]     (< 50000)
//   kind 1 (prim): src = prim_types[j]   (< 16)
//   kind 2 (mod):  src = mod_ids[j]      (< 16)
// ---------------------------------------------------------------------------
__global__ void set_flags_kernel(
    const int* __restrict__ id_node,   const int* __restrict__ id_ident,
    const int* __restrict__ prim_node, const int* __restrict__ prim_types,
    const int* __restrict__ mod_node,  const int* __restrict__ mod_ids)
{
    int i = blockIdx.x * blockDim.x + threadIdx.x;
    if (i < N_ID) {
        g_flag[id_node[i]] = id_ident[i];                    // kind 0
    } else if (i < N_ID + N_PRIM) {
        int j = i - N_ID;
        g_flag[prim_node[j]] = (1 << 28) | prim_types[j];    // kind 1
    } else if (i < N_ID + N_PRIM + N_MOD) {
        int j = i - N_ID - N_PRIM;
        g_flag[mod_node[j]] = (2 << 28) | mod_ids[j];        // kind 2
    }
}

// ---------------------------------------------------------------------------
// 32 threads per node, 2 float4 per thread (c, c+32). Streaming stores keep
// g_Y resident in L2 for the gathers. Grid exact: 500000*32/256 = 62500.
// ---------------------------------------------------------------------------
__global__ __launch_bounds__(256) void finalize_kernel(
    const float4* __restrict__ tbl4,
    const int* __restrict__ types,
    float4* __restrict__ out4)
{
    long long idx = (long long)blockIdx.x * 256 + threadIdx.x;
    int node = (int)(idx >> 5);
    int lane = (int)(idx & 31);

    int f = g_flag[node];
    int t = types[node];
    float4 r0, r1;

    if (f < 0) {
        r0 = tbl4[t * 64 + lane];
        r1 = tbl4[t * 64 + lane + 32];
    } else {
        int kind = f >> 28;
        int src  = f & 0x0FFFFFFF;
        const float4* xb;
        const float4* yb;
        if (kind == 0)      { xb = (const float4*)g_Y; yb = (const float4*)g_Tid;   }
        else if (kind == 1) { xb = (const float4*)g_P; yb = (const float4*)g_Tprim; }
        else                { xb = (const float4*)g_M; yb = (const float4*)g_Tmod;  }
        float4 x0 = xb[(size_t)src * 64 + lane];
        float4 x1 = xb[(size_t)src * 64 + lane + 32];
        float4 y0 = yb[t * 64 + lane];
        float4 y1 = yb[t * 64 + lane + 32];
        r0 = make_float4(x0.x + y0.x, x0.y + y0.y, x0.z + y0.z, x0.w + y0.w);
        r1 = make_float4(x1.x + y1.x, x1.y + y1.y, x1.z + y1.z, x1.w + y1.w);
    }
    __stcs(&out4[(size_t)node * 64 + lane], r0);
    __stcs(&out4[(size_t)node * 64 + lane + 32], r1);
}

extern "C" void kernel_launch(void* const* d_in, const int* in_sizes, int n_in,
                              void* d_out, int out_size)
{
    const float* identifiers = (const float*)d_in[0];
    const float* node_table  = (const float*)d_in[1];
    const float* prim_table  = (const float*)d_in[2];
    const float* mod_table   = (const float*)d_in[3];
    const float* W_id        = (const float*)d_in[4];
    const float* b_id        = (const float*)d_in[5];
    const float* W_prim      = (const float*)d_in[6];
    const float* b_prim      = (const float*)d_in[7];
    const float* W_mod       = (const float*)d_in[8];
    const float* b_mod       = (const float*)d_in[9];
    const int*   types       = (const int*)d_in[10];
    const int*   id_ident    = (const int*)d_in[11];
    const int*   id_node     = (const int*)d_in[12];
    const int*   prim_types  = (const int*)d_in[13];
    const int*   prim_node   = (const int*)d_in[14];
    const int*   mod_ids     = (const int*)d_in[15];
    const int*   mod_node    = (const int*)d_in[16];
    float*       out         = (float*)d_out;

    static bool attr_set = false;
    if (!attr_set) {
        cudaFuncSetAttribute(gemm_mma_kernel,
                             cudaFuncAttributeMaxDynamicSharedMemorySize,
                             GEMM_SMEM_BYTES);
        attr_set = true;
    }

    // Precomputes + flag init (one launch)
    precompute_kernel<<<PRE_BLOCKS + FLAG_BLOCKS, 256>>>(
        node_table, prim_table, mod_table,
        W_id, b_id, W_prim, b_prim, W_mod, b_mod);

    // Flags: scatter resolved (kind, src) per leaf node
    {
        int total = N_ID + N_PRIM + N_MOD;
        set_flags_kernel<<<(total + 255) / 256, 256>>>(
            id_node, id_ident, prim_node, prim_types, mod_node, mod_ids);
    }

    // Main GEMM on HMMA tf32 + cp.async pipeline
    {
        dim3 grid((N_IDENT + BM - 1) / BM, 256 / BN);   // 391 x 2
        gemm_mma_kernel<<<grid, 256, GEMM_SMEM_BYTES>>>(identifiers, W_id);
    }

    // Fused output pass (exact grid, no bounds check)
    finalize_kernel<<<62500, 256>>>((const float4*)node_table, types, (float4*)out);
}